// round 2
// baseline (speedup 1.0000x reference)
#include <cuda_runtime.h>
#include <math.h>

#define NN   50000
#define EE   800000
#define FE   32
#define HH   128
#define GG   64

// ---------------- scratch (device globals: no allocs allowed) ----------------
__device__ float    g_bufA[NN * HH];   // xw (conv1), then xw2 (conv2)
__device__ float    g_bufB[NN * HH];   // h (post conv1+elu, then += attention agg)
__device__ float    g_bufC[NN * HH];   // conv accumulation buffer (pre-elu)
__device__ float    g_dinv[NN];        // degree, then rsqrt(degree)
__device__ float    g_ar[NN];
__device__ float    g_ac[NN];
__device__ unsigned g_maxbits;
__device__ float    g_sumexp;
__device__ float    g_pooled[GG * HH];
__device__ float    g_cnt[GG];

// ordered-uint key for float atomicMax
__device__ __forceinline__ unsigned fkey(float f) {
    unsigned b = __float_as_uint(f);
    return (b & 0x80000000u) ? ~b : (b | 0x80000000u);
}
__device__ __forceinline__ float fdecode(unsigned k) {
    unsigned b = (k & 0x80000000u) ? (k ^ 0x80000000u) : ~k;
    return __uint_as_float(b);
}
__device__ __forceinline__ float eluf(float x) {
    return x > 0.f ? x : (expf(x) - 1.f);
}

// ---------------- init ----------------
__global__ void k_init() {
    int i = blockIdx.x * blockDim.x + threadIdx.x;
    // Reference adds self-loops TWICE (explicit add_self_loops + GCNConv's own):
    // deg[i] = indeg[i] + 2.
    if (i < NN)      g_dinv[i]   = 2.0f;
    if (i < GG * HH) g_pooled[i] = 0.0f;
    if (i < GG)      g_cnt[i]    = 0.0f;
    if (i == 0) { g_maxbits = 0u; g_sumexp = 0.0f; }
}

__global__ void k_deg_count(const int* __restrict__ ei) {
    int e = blockIdx.x * blockDim.x + threadIdx.x;
    if (e < EE) atomicAdd(&g_dinv[ei[EE + e]], 1.0f);   // count on col
}

__global__ void k_dinv() {
    int i = blockIdx.x * blockDim.x + threadIdx.x;
    if (i < NN) g_dinv[i] = rsqrtf(g_dinv[i]);
}

__global__ void k_cnt(const int* __restrict__ batch) {
    int i = blockIdx.x * blockDim.x + threadIdx.x;
    if (i < NN) atomicAdd(&g_cnt[batch[i]], 1.0f);
}

// ---------------- generic [nrows,128] @ [128,128] GEMM ----------------
// 256 threads, tile 64 rows x 128 cols, K chunks of 32, per-thread 4x8 regs.
__global__ void __launch_bounds__(256) k_gemm(const float* __restrict__ A,
                                              const float* __restrict__ W,
                                              float* __restrict__ out, int nrows) {
    __shared__ float sA[64 * 32];
    __shared__ float sW[32 * 128];
    int tid = threadIdx.x;
    int r0  = blockIdx.x * 64;
    int ce  = tid & 15;        // col group: cols ce*8 .. ce*8+7
    int re  = tid >> 4;        // row group: rows re*4 .. re*4+3

    float acc[4][8];
#pragma unroll
    for (int r = 0; r < 4; r++)
#pragma unroll
        for (int c = 0; c < 8; c++) acc[r][c] = 0.f;

    for (int kc = 0; kc < 4; kc++) {
#pragma unroll
        for (int i = 0; i < 8; i++) {
            int lin = tid + i * 256;
            int r = lin >> 5, k = lin & 31;
            int gr = r0 + r;
            sA[lin] = (gr < nrows) ? A[gr * 128 + kc * 32 + k] : 0.f;
        }
#pragma unroll
        for (int i = 0; i < 16; i++) {
            int lin = tid + i * 256;
            int kk = lin >> 7, c = lin & 127;
            sW[lin] = W[(kc * 32 + kk) * 128 + c];
        }
        __syncthreads();
#pragma unroll
        for (int k = 0; k < 32; k++) {
            float a[4], b[8];
#pragma unroll
            for (int r = 0; r < 4; r++) a[r] = sA[(re * 4 + r) * 32 + k];
#pragma unroll
            for (int c = 0; c < 8; c++) b[c] = sW[k * 128 + ce * 8 + c];
#pragma unroll
            for (int r = 0; r < 4; r++)
#pragma unroll
                for (int c = 0; c < 8; c++) acc[r][c] += a[r] * b[c];
        }
        __syncthreads();
    }
#pragma unroll
    for (int r = 0; r < 4; r++) {
        int gr = r0 + re * 4 + r;
        if (gr < nrows) {
#pragma unroll
            for (int c = 0; c < 8; c++) out[gr * 128 + ce * 8 + c] = acc[r][c];
        }
    }
}

// ---------------- GCN conv pieces ----------------
// Self-loop appears TWICE: out[i][j] = 2*xw[i][j]*dinv[i]^2 + b[j]
__global__ void k_conv_init(const float* __restrict__ xw, const float* __restrict__ b,
                            float* __restrict__ out) {
    int idx = blockIdx.x * blockDim.x + threadIdx.x;
    if (idx < NN * HH) {
        int n = idx >> 7;
        float d = g_dinv[n];
        out[idx] = 2.0f * xw[idx] * d * d + b[idx & 127];
    }
}

// per edge: out[col] += xw[row] * dinv[row]*dinv[col]   (thread = edge x 4 cols)
__global__ void __launch_bounds__(256) k_conv_scatter(const int* __restrict__ ei,
                                                      const float* __restrict__ xw,
                                                      float* __restrict__ out) {
    long long idx = (long long)blockIdx.x * blockDim.x + threadIdx.x;
    int e = (int)(idx >> 5);
    int q = (int)(idx & 31);
    if (e >= EE) return;
    int r = __ldg(&ei[e]);
    int c = __ldg(&ei[EE + e]);
    float nrm = g_dinv[r] * g_dinv[c];
    float4 v = *(const float4*)(xw + (long long)r * 128 + q * 4);
    float* dst = out + (long long)c * 128 + q * 4;
    atomicAdd(dst + 0, v.x * nrm);
    atomicAdd(dst + 1, v.y * nrm);
    atomicAdd(dst + 2, v.z * nrm);
    atomicAdd(dst + 3, v.w * nrm);
}

__global__ void k_elu(const float* __restrict__ in, float* __restrict__ out) {
    int idx = blockIdx.x * blockDim.x + threadIdx.x;
    if (idx < NN * HH) out[idx] = eluf(in[idx]);
}

// ---------------- attention ----------------
// per-node dot products with the two halves of Watt
__global__ void k_att_dots(const float* __restrict__ h, const float* __restrict__ Watt) {
    int warp = (blockIdx.x * blockDim.x + threadIdx.x) >> 5;
    int lane = threadIdx.x & 31;
    if (warp >= NN) return;
    const float* hr = h + (long long)warp * 128;
    float s1 = 0.f, s2 = 0.f;
#pragma unroll
    for (int j = lane; j < 128; j += 32) {
        float v = hr[j];
        s1 += v * Watt[j];
        s2 += v * Watt[128 + j];
    }
#pragma unroll
    for (int o = 16; o > 0; o >>= 1) {
        s1 += __shfl_down_sync(0xffffffffu, s1, o);
        s2 += __shfl_down_sync(0xffffffffu, s2, o);
    }
    if (lane == 0) { g_ar[warp] = s1; g_ac[warp] = s2; }
}

__global__ void k_logit_max(const int* __restrict__ ei) {
    __shared__ float red[256];
    const int total = EE + NN;
    float m = -1e30f;
    for (int i = blockIdx.x * blockDim.x + threadIdx.x; i < total;
         i += gridDim.x * blockDim.x) {
        int r, c;
        if (i < EE) { r = ei[i]; c = ei[EE + i]; } else { r = c = i - EE; }
        m = fmaxf(m, g_ar[r] + g_ac[c]);
    }
    red[threadIdx.x] = m;
    __syncthreads();
    for (int s = 128; s > 0; s >>= 1) {
        if (threadIdx.x < s) red[threadIdx.x] = fmaxf(red[threadIdx.x], red[threadIdx.x + s]);
        __syncthreads();
    }
    if (threadIdx.x == 0) atomicMax(&g_maxbits, fkey(red[0]));
}

__global__ void k_logit_sum(const int* __restrict__ ei) {
    __shared__ float red[256];
    const int total = EE + NN;
    float gm = fdecode(g_maxbits);
    float s = 0.f;
    for (int i = blockIdx.x * blockDim.x + threadIdx.x; i < total;
         i += gridDim.x * blockDim.x) {
        int r, c;
        if (i < EE) { r = ei[i]; c = ei[EE + i]; } else { r = c = i - EE; }
        s += expf(g_ar[r] + g_ac[c] - gm);
    }
    red[threadIdx.x] = s;
    __syncthreads();
    for (int o = 128; o > 0; o >>= 1) {
        if (threadIdx.x < o) red[threadIdx.x] += red[threadIdx.x + o];
        __syncthreads();
    }
    if (threadIdx.x == 0) atomicAdd(&g_sumexp, red[0]);
}

// ---------------- fused edge MLP + attention-weighted scatter ----------------
// Per block: 64 edges. hidden = relu(attr@We1+be1); ea = hidden@We2+be2;
// h[row[e]] += att[e]*ea[e]  (atomics).
#define EDGE_SMEM_FLOATS (64 * 32 + 32 * 128 + 64 * 128 + 32 * 128 + 64)
__global__ void __launch_bounds__(256) k_edge_mlp_scatter(
        const float* __restrict__ eattr, const int* __restrict__ ei,
        const float* __restrict__ We1, const float* __restrict__ be1,
        const float* __restrict__ We2, const float* __restrict__ be2,
        float* __restrict__ h) {
    extern __shared__ float sm[];
    float* sAttr = sm;                       // 64 x 32
    float* sW1   = sAttr + 64 * 32;          // 32 x 128
    float* sHid  = sW1 + 32 * 128;           // 64 x 128
    float* sW2   = sHid + 64 * 128;          // 32 x 128 (K-chunk)
    float* sAtt  = sW2 + 32 * 128;           // 64

    int tid = threadIdx.x;
    int e0  = blockIdx.x * 64;
    int ce  = tid & 15;
    int re  = tid >> 4;

    // load attr tile + We1
#pragma unroll
    for (int i = 0; i < 8; i++) {
        int lin = tid + i * 256;
        int r = lin >> 5, k = lin & 31;
        sAttr[lin] = eattr[(long long)(e0 + r) * 32 + k];
    }
#pragma unroll
    for (int i = 0; i < 16; i++) {
        int lin = tid + i * 256;
        sW1[lin] = We1[lin];
    }
    __syncthreads();

    // GEMM1: hidden = relu(attr @ We1 + be1), K=32
    float acc[4][8];
#pragma unroll
    for (int r = 0; r < 4; r++)
#pragma unroll
        for (int c = 0; c < 8; c++) acc[r][c] = be1[ce * 8 + c];
#pragma unroll
    for (int k = 0; k < 32; k++) {
        float a[4], b[8];
#pragma unroll
        for (int r = 0; r < 4; r++) a[r] = sAttr[(re * 4 + r) * 32 + k];
#pragma unroll
        for (int c = 0; c < 8; c++) b[c] = sW1[k * 128 + ce * 8 + c];
#pragma unroll
        for (int r = 0; r < 4; r++)
#pragma unroll
            for (int c = 0; c < 8; c++) acc[r][c] += a[r] * b[c];
    }
#pragma unroll
    for (int r = 0; r < 4; r++)
#pragma unroll
        for (int c = 0; c < 8; c++)
            sHid[(re * 4 + r) * 128 + ce * 8 + c] = fmaxf(acc[r][c], 0.f);

    // att per edge (softmax weight); batt cancels in softmax
    if (tid < 64) {
        int ge = e0 + tid;
        int r = ei[ge], c = ei[EE + ge];
        float gm = fdecode(g_maxbits);
        sAtt[tid] = expf(g_ar[r] + g_ac[c] - gm) / g_sumexp;
    }

    // GEMM2: ea = hidden @ We2 + be2, K=128 in chunks of 32
    float acc2[4][8];
#pragma unroll
    for (int r = 0; r < 4; r++)
#pragma unroll
        for (int c = 0; c < 8; c++) acc2[r][c] = be2[ce * 8 + c];

    for (int kc = 0; kc < 4; kc++) {
        __syncthreads();
#pragma unroll
        for (int i = 0; i < 16; i++) {
            int lin = tid + i * 256;
            int kk = lin >> 7, c = lin & 127;
            sW2[lin] = We2[(kc * 32 + kk) * 128 + c];
        }
        __syncthreads();
#pragma unroll
        for (int k = 0; k < 32; k++) {
            float a[4], b[8];
#pragma unroll
            for (int r = 0; r < 4; r++) a[r] = sHid[(re * 4 + r) * 128 + kc * 32 + k];
#pragma unroll
            for (int c = 0; c < 8; c++) b[c] = sW2[k * 128 + ce * 8 + c];
#pragma unroll
            for (int r = 0; r < 4; r++)
#pragma unroll
                for (int c = 0; c < 8; c++) acc2[r][c] += a[r] * b[c];
        }
    }

    // scatter: h[row[e]][:] += att[e] * ea[e][:]
#pragma unroll
    for (int r = 0; r < 4; r++) {
        int le = re * 4 + r;
        int ge = e0 + le;
        int dest = ei[ge];                 // row
        float at = sAtt[le];
        float* dst = h + (long long)dest * 128 + ce * 8;
#pragma unroll
        for (int c = 0; c < 8; c++) atomicAdd(dst + c, at * acc2[r][c]);
    }
}

// ---------------- pooling + fc ----------------
// thread = (node-chunk of 8, column j). batch is sorted -> run-accumulate.
__global__ void k_elu_pool(const float* __restrict__ outC, const int* __restrict__ batch) {
    int idx = blockIdx.x * blockDim.x + threadIdx.x;
    int totalChunks = (NN + 7) / 8;
    if (idx >= totalChunks * 128) return;
    int j  = idx & 127;
    int nb = (idx >> 7) * 8;
    float acc = 0.f;
    int cur = -1;
    for (int t = 0; t < 8; t++) {
        int n = nb + t;
        if (n >= NN) break;
        int g = batch[n];
        float v = eluf(outC[(long long)n * 128 + j]);
        if (g != cur) {
            if (cur >= 0) atomicAdd(&g_pooled[cur * 128 + j], acc);
            cur = g; acc = 0.f;
        }
        acc += v;
    }
    if (cur >= 0) atomicAdd(&g_pooled[cur * 128 + j], acc);
}

__global__ void k_fc(const float* __restrict__ Wfc, const float* __restrict__ bfc,
                     float* __restrict__ out) {
    int g = threadIdx.x;
    if (g >= GG) return;
    float s = 0.f;
#pragma unroll
    for (int j = 0; j < 128; j++) s += g_pooled[g * 128 + j] * Wfc[j];
    out[g] = s / fmaxf(g_cnt[g], 1.0f) + bfc[0];
}

// ---------------- launch ----------------
extern "C" void kernel_launch(void* const* d_in, const int* in_sizes, int n_in,
                              void* d_out, int out_size) {
    const float* x     = (const float*)d_in[0];
    const int*   ei    = (const int*)d_in[1];
    const float* eattr = (const float*)d_in[2];
    const int*   batch = (const int*)d_in[3];
    const float* W1    = (const float*)d_in[4];
    const float* b1    = (const float*)d_in[5];
    const float* W2    = (const float*)d_in[6];
    const float* b2    = (const float*)d_in[7];
    const float* We1   = (const float*)d_in[8];
    const float* be1   = (const float*)d_in[9];
    const float* We2   = (const float*)d_in[10];
    const float* be2   = (const float*)d_in[11];
    const float* Watt  = (const float*)d_in[12];
    // d_in[13] = batt (cancels in softmax)
    const float* Wfc   = (const float*)d_in[14];
    const float* bfc   = (const float*)d_in[15];
    float* out = (float*)d_out;

    float *bufA, *bufB, *bufC;
    cudaGetSymbolAddress((void**)&bufA, g_bufA);
    cudaGetSymbolAddress((void**)&bufB, g_bufB);
    cudaGetSymbolAddress((void**)&bufC, g_bufC);

    static bool attrSet = false;
    if (!attrSet) {
        cudaFuncSetAttribute(k_edge_mlp_scatter,
                             cudaFuncAttributeMaxDynamicSharedMemorySize,
                             EDGE_SMEM_FLOATS * 4);
        attrSet = true;
    }

    const int T = 256;
    int nhBlocks = (NN * HH + T - 1) / T;

    k_init<<<(NN + T - 1) / T, T>>>();
    k_deg_count<<<(EE + T - 1) / T, T>>>(ei);
    k_dinv<<<(NN + T - 1) / T, T>>>();
    k_cnt<<<(NN + T - 1) / T, T>>>(batch);

    // conv1: h = elu(D^-1/2 A D^-1/2 (x@W1) + b1)
    k_gemm<<<(NN + 63) / 64, 256>>>(x, W1, bufA, NN);
    k_conv_init<<<nhBlocks, T>>>(bufA, b1, bufC);
    {
        long long tcount = (long long)EE * 32;
        k_conv_scatter<<<(unsigned)((tcount + T - 1) / T), T>>>(ei, bufA, bufC);
    }
    k_elu<<<nhBlocks, T>>>(bufC, bufB);

    // attention: global softmax over E+N edge logits
    k_att_dots<<<(NN * 32 + T - 1) / T, T>>>(bufB, Watt);
    k_logit_max<<<512, 256>>>(ei);
    k_logit_sum<<<512, 256>>>(ei);

    // fused edge MLP + weighted scatter-add into h
    k_edge_mlp_scatter<<<EE / 64, 256, EDGE_SMEM_FLOATS * 4>>>(
        eattr, ei, We1, be1, We2, be2, bufB);

    // conv2
    k_gemm<<<(NN + 63) / 64, 256>>>(bufB, W2, bufA, NN);
    k_conv_init<<<nhBlocks, T>>>(bufA, b2, bufC);
    {
        long long tcount = (long long)EE * 32;
        k_conv_scatter<<<(unsigned)((tcount + T - 1) / T), T>>>(ei, bufA, bufC);
    }

    // elu + global mean pool + fc
    {
        int totalChunks = (NN + 7) / 8;
        k_elu_pool<<<(totalChunks * 128 + T - 1) / T, T>>>(bufC, batch);
    }
    k_fc<<<1, 64>>>(Wfc, bfc, out);
}

// round 3
// speedup vs baseline: 2.5206x; 2.5206x over previous
#include <cuda_runtime.h>
#include <math.h>

#define NN   50000
#define EE   800000
#define FE   32
#define HH   128
#define GG   64

// ---------------- scratch (device globals: no allocs allowed) ----------------
__device__ float    g_bufA[NN * HH];   // xw (raw GEMM output), conv1 & conv2
__device__ float    g_bufB[NN * HH];   // h
__device__ float    g_bufC[NN * HH];   // conv accumulator, then agg buffer
__device__ float    g_dinv[NN];
__device__ float    g_ar[NN];
__device__ float    g_ac[NN];
__device__ float    g_attsum[NN];
__device__ unsigned g_maxbits;
__device__ float    g_sumexp;
__device__ float    g_pooled[GG * HH];
__device__ float    g_cnt[GG];

// ordered-uint key for float atomicMax
__device__ __forceinline__ unsigned fkey(float f) {
    unsigned b = __float_as_uint(f);
    return (b & 0x80000000u) ? ~b : (b | 0x80000000u);
}
__device__ __forceinline__ float fdecode(unsigned k) {
    unsigned b = (k & 0x80000000u) ? (k ^ 0x80000000u) : ~k;
    return __uint_as_float(b);
}
__device__ __forceinline__ float eluf(float x) {
    return x > 0.f ? x : (expf(x) - 1.f);
}
// vectorized reduction (no return) — 1 instruction for 4 floats, sm_90+
__device__ __forceinline__ void red4(float* addr, float a, float b, float c, float d) {
    asm volatile("red.global.add.v4.f32 [%0], {%1,%2,%3,%4};"
                 :: "l"(addr), "f"(a), "f"(b), "f"(c), "f"(d) : "memory");
}

// ---------------- init ----------------
__global__ void k_init() {
    int i = blockIdx.x * blockDim.x + threadIdx.x;
    // double self-loop: explicit add_self_loops + GCNConv's internal one
    if (i < NN)      { g_dinv[i] = 2.0f; g_attsum[i] = 0.0f; }
    if (i < GG * HH) g_pooled[i] = 0.0f;
    if (i < GG)      g_cnt[i]    = 0.0f;
    if (i == 0) { g_maxbits = 0u; g_sumexp = 0.0f; }
}

__global__ void k_deg_count(const int* __restrict__ ei) {
    int e = blockIdx.x * blockDim.x + threadIdx.x;
    if (e < EE) atomicAdd(&g_dinv[ei[EE + e]], 1.0f);
}

__global__ void k_dinv() {
    int i = blockIdx.x * blockDim.x + threadIdx.x;
    if (i < NN) g_dinv[i] = rsqrtf(g_dinv[i]);
}

// block-shared histogram (batch sorted -> heavy per-value contention globally)
__global__ void k_cnt(const int* __restrict__ batch) {
    __shared__ float sh[GG];
    if (threadIdx.x < GG) sh[threadIdx.x] = 0.f;
    __syncthreads();
    int i = blockIdx.x * blockDim.x + threadIdx.x;
    if (i < NN) atomicAdd(&sh[batch[i]], 1.0f);
    __syncthreads();
    if (threadIdx.x < GG && sh[threadIdx.x] != 0.f)
        atomicAdd(&g_cnt[threadIdx.x], sh[threadIdx.x]);
}

// ---------------- GEMM [nrows,128]@[128,128], conv epilogue ----------------
// writes raw xw AND the conv accumulator init: 2*dinv^2*xw + b
__global__ void __launch_bounds__(256) k_gemm_conv(const float* __restrict__ A,
                                                   const float* __restrict__ W,
                                                   const float* __restrict__ bias,
                                                   float* __restrict__ xw_out,
                                                   float* __restrict__ acc_out,
                                                   int nrows) {
    __shared__ float sA[64 * 32];
    __shared__ float sW[32 * 128];
    int tid = threadIdx.x;
    int r0  = blockIdx.x * 64;
    int ce  = tid & 15;
    int re  = tid >> 4;

    float acc[4][8];
#pragma unroll
    for (int r = 0; r < 4; r++)
#pragma unroll
        for (int c = 0; c < 8; c++) acc[r][c] = 0.f;

    for (int kc = 0; kc < 4; kc++) {
#pragma unroll
        for (int i = 0; i < 8; i++) {
            int lin = tid + i * 256;
            int r = lin >> 5, k = lin & 31;
            int gr = r0 + r;
            sA[lin] = (gr < nrows) ? A[gr * 128 + kc * 32 + k] : 0.f;
        }
#pragma unroll
        for (int i = 0; i < 16; i++) {
            int lin = tid + i * 256;
            int kk = lin >> 7, c = lin & 127;
            sW[lin] = W[(kc * 32 + kk) * 128 + c];
        }
        __syncthreads();
#pragma unroll
        for (int k = 0; k < 32; k++) {
            float a[4], b[8];
#pragma unroll
            for (int r = 0; r < 4; r++) a[r] = sA[(re * 4 + r) * 32 + k];
#pragma unroll
            for (int c = 0; c < 8; c++) b[c] = sW[k * 128 + ce * 8 + c];
#pragma unroll
            for (int r = 0; r < 4; r++)
#pragma unroll
                for (int c = 0; c < 8; c++) acc[r][c] += a[r] * b[c];
        }
        __syncthreads();
    }
#pragma unroll
    for (int r = 0; r < 4; r++) {
        int gr = r0 + re * 4 + r;
        if (gr < nrows) {
            float d = g_dinv[gr];
            float s = 2.0f * d * d;
#pragma unroll
            for (int c = 0; c < 8; c++) {
                float v = acc[r][c];
                xw_out[gr * 128 + ce * 8 + c]  = v;
                acc_out[gr * 128 + ce * 8 + c] = s * v + bias[ce * 8 + c];
            }
        }
    }
}

// GEMM applying We2 to the scattered hidden-agg:  h += agg@We2 + attsum*be2
__global__ void __launch_bounds__(256) k_gemm_apply(const float* __restrict__ A,
                                                    const float* __restrict__ W,
                                                    const float* __restrict__ be2,
                                                    float* __restrict__ h,
                                                    int nrows) {
    __shared__ float sA[64 * 32];
    __shared__ float sW[32 * 128];
    int tid = threadIdx.x;
    int r0  = blockIdx.x * 64;
    int ce  = tid & 15;
    int re  = tid >> 4;

    float acc[4][8];
#pragma unroll
    for (int r = 0; r < 4; r++)
#pragma unroll
        for (int c = 0; c < 8; c++) acc[r][c] = 0.f;

    for (int kc = 0; kc < 4; kc++) {
#pragma unroll
        for (int i = 0; i < 8; i++) {
            int lin = tid + i * 256;
            int r = lin >> 5, k = lin & 31;
            int gr = r0 + r;
            sA[lin] = (gr < nrows) ? A[gr * 128 + kc * 32 + k] : 0.f;
        }
#pragma unroll
        for (int i = 0; i < 16; i++) {
            int lin = tid + i * 256;
            int kk = lin >> 7, c = lin & 127;
            sW[lin] = W[(kc * 32 + kk) * 128 + c];
        }
        __syncthreads();
#pragma unroll
        for (int k = 0; k < 32; k++) {
            float a[4], b[8];
#pragma unroll
            for (int r = 0; r < 4; r++) a[r] = sA[(re * 4 + r) * 32 + k];
#pragma unroll
            for (int c = 0; c < 8; c++) b[c] = sW[k * 128 + ce * 8 + c];
#pragma unroll
            for (int r = 0; r < 4; r++)
#pragma unroll
                for (int c = 0; c < 8; c++) acc[r][c] += a[r] * b[c];
        }
        __syncthreads();
    }
#pragma unroll
    for (int r = 0; r < 4; r++) {
        int gr = r0 + re * 4 + r;
        if (gr < nrows) {
            float as = g_attsum[gr];
#pragma unroll
            for (int c = 0; c < 8; c++) {
                int o = gr * 128 + ce * 8 + c;
                h[o] += acc[r][c] + as * be2[ce * 8 + c];
            }
        }
    }
}

// ---------------- conv scatter: out[col] += xw[row]*dinv[row]*dinv[col] ----------------
__global__ void __launch_bounds__(256) k_conv_scatter(const int* __restrict__ ei,
                                                      const float* __restrict__ xw,
                                                      float* __restrict__ out) {
    long long idx = (long long)blockIdx.x * blockDim.x + threadIdx.x;
    int e = (int)(idx >> 5);
    int q = (int)(idx & 31);
    if (e >= EE) return;
    int r = __ldg(&ei[e]);
    int c = __ldg(&ei[EE + e]);
    float nrm = g_dinv[r] * g_dinv[c];
    float4 v = *(const float4*)(xw + (long long)r * 128 + q * 4);
    red4(out + (long long)c * 128 + q * 4, v.x * nrm, v.y * nrm, v.z * nrm, v.w * nrm);
}

// ---------------- fused elu + attention dots + zero agg buffer ----------------
// warp per node: h = elu(convAcc); write h; zero convAcc (becomes agg buf);
// compute ar = h.Watt[:128], ac = h.Watt[128:]
__global__ void k_elu_att(const float* __restrict__ convAcc, float* __restrict__ h,
                          float* __restrict__ aggZero, const float* __restrict__ Watt) {
    int warp = (blockIdx.x * blockDim.x + threadIdx.x) >> 5;
    int lane = threadIdx.x & 31;
    if (warp >= NN) return;
    long long base = (long long)warp * 128 + lane * 4;
    float4 v = *(const float4*)(convAcc + base);
    float4 e4;
    e4.x = eluf(v.x); e4.y = eluf(v.y); e4.z = eluf(v.z); e4.w = eluf(v.w);
    *(float4*)(h + base) = e4;
    *(float4*)(aggZero + base) = make_float4(0.f, 0.f, 0.f, 0.f);
    float4 w1 = *(const float4*)(Watt + lane * 4);
    float4 w2 = *(const float4*)(Watt + 128 + lane * 4);
    float s1 = e4.x * w1.x + e4.y * w1.y + e4.z * w1.z + e4.w * w1.w;
    float s2 = e4.x * w2.x + e4.y * w2.y + e4.z * w2.z + e4.w * w2.w;
#pragma unroll
    for (int o = 16; o > 0; o >>= 1) {
        s1 += __shfl_down_sync(0xffffffffu, s1, o);
        s2 += __shfl_down_sync(0xffffffffu, s2, o);
    }
    if (lane == 0) { g_ar[warp] = s1; g_ac[warp] = s2; }
}

__global__ void k_logit_max(const int* __restrict__ ei) {
    __shared__ float red[256];
    const int total = EE + NN;
    float m = -1e30f;
    for (int i = blockIdx.x * blockDim.x + threadIdx.x; i < total;
         i += gridDim.x * blockDim.x) {
        int r, c;
        if (i < EE) { r = ei[i]; c = ei[EE + i]; } else { r = c = i - EE; }
        m = fmaxf(m, g_ar[r] + g_ac[c]);
    }
    red[threadIdx.x] = m;
    __syncthreads();
    for (int s = 128; s > 0; s >>= 1) {
        if (threadIdx.x < s) red[threadIdx.x] = fmaxf(red[threadIdx.x], red[threadIdx.x + s]);
        __syncthreads();
    }
    if (threadIdx.x == 0) atomicMax(&g_maxbits, fkey(red[0]));
}

__global__ void k_logit_sum(const int* __restrict__ ei) {
    __shared__ float red[256];
    const int total = EE + NN;
    float gm = fdecode(g_maxbits);
    float s = 0.f;
    for (int i = blockIdx.x * blockDim.x + threadIdx.x; i < total;
         i += gridDim.x * blockDim.x) {
        int r, c;
        if (i < EE) { r = ei[i]; c = ei[EE + i]; } else { r = c = i - EE; }
        s += expf(g_ar[r] + g_ac[c] - gm);
    }
    red[threadIdx.x] = s;
    __syncthreads();
    for (int o = 128; o > 0; o >>= 1) {
        if (threadIdx.x < o) red[threadIdx.x] += red[threadIdx.x + o];
        __syncthreads();
    }
    if (threadIdx.x == 0) atomicAdd(&g_sumexp, red[0]);
}

// ---------------- fused edge MLP (layer 1 only) + weighted hidden scatter ------
// We2 is applied NODE-side afterwards (linearity): scatter att*relu(attr@We1+be1).
__global__ void __launch_bounds__(256) k_edge_hidden_scatter(
        const float* __restrict__ eattr, const int* __restrict__ ei,
        const float* __restrict__ We1, const float* __restrict__ be1,
        float* __restrict__ agg) {
    __shared__ float sAttr[64 * 32];
    __shared__ float sW1[32 * 128];
    __shared__ float sAtt[64];
    __shared__ int   sRow[64];

    int tid = threadIdx.x;
    int e0  = blockIdx.x * 64;
    int ce  = tid & 15;
    int re  = tid >> 4;

#pragma unroll
    for (int i = 0; i < 8; i++) {
        int lin = tid + i * 256;
        sAttr[lin] = eattr[(long long)e0 * 32 + lin];
    }
#pragma unroll
    for (int i = 0; i < 16; i++) {
        int lin = tid + i * 256;
        sW1[lin] = We1[lin];
    }
    // attention weights for this block's 64 edges (batt cancels in softmax)
    if (tid < 64) {
        int ge = e0 + tid;
        int r = ei[ge], c = ei[EE + ge];
        float gm = fdecode(g_maxbits);
        float at = expf(g_ar[r] + g_ac[c] - gm) / g_sumexp;
        sAtt[tid] = at;
        sRow[tid] = r;
        atomicAdd(&g_attsum[r], at);
    }
    __syncthreads();

    // hidden = relu(attr @ We1 + be1), K=32
    float acc[4][8];
#pragma unroll
    for (int r = 0; r < 4; r++)
#pragma unroll
        for (int c = 0; c < 8; c++) acc[r][c] = be1[ce * 8 + c];
#pragma unroll
    for (int k = 0; k < 32; k++) {
        float a[4], b[8];
#pragma unroll
        for (int r = 0; r < 4; r++) a[r] = sAttr[(re * 4 + r) * 32 + k];
#pragma unroll
        for (int c = 0; c < 8; c++) b[c] = sW1[k * 128 + ce * 8 + c];
#pragma unroll
        for (int r = 0; r < 4; r++)
#pragma unroll
            for (int c = 0; c < 8; c++) acc[r][c] += a[r] * b[c];
    }

    // scatter straight from registers: agg[row[e]] += att[e]*relu(hidden)
#pragma unroll
    for (int r = 0; r < 4; r++) {
        int le = re * 4 + r;
        float at = sAtt[le];
        float* dst = agg + (long long)sRow[le] * 128 + ce * 8;
        red4(dst,     at * fmaxf(acc[r][0], 0.f), at * fmaxf(acc[r][1], 0.f),
                      at * fmaxf(acc[r][2], 0.f), at * fmaxf(acc[r][3], 0.f));
        red4(dst + 4, at * fmaxf(acc[r][4], 0.f), at * fmaxf(acc[r][5], 0.f),
                      at * fmaxf(acc[r][6], 0.f), at * fmaxf(acc[r][7], 0.f));
    }
}

// ---------------- pooling + fc ----------------
__global__ void k_elu_pool(const float* __restrict__ outC, const int* __restrict__ batch) {
    int idx = blockIdx.x * blockDim.x + threadIdx.x;
    int totalChunks = (NN + 7) / 8;
    if (idx >= totalChunks * 128) return;
    int j  = idx & 127;
    int nb = (idx >> 7) * 8;
    float acc = 0.f;
    int cur = -1;
    for (int t = 0; t < 8; t++) {
        int n = nb + t;
        if (n >= NN) break;
        int g = batch[n];
        float v = eluf(outC[(long long)n * 128 + j]);
        if (g != cur) {
            if (cur >= 0) atomicAdd(&g_pooled[cur * 128 + j], acc);
            cur = g; acc = 0.f;
        }
        acc += v;
    }
    if (cur >= 0) atomicAdd(&g_pooled[cur * 128 + j], acc);
}

__global__ void k_fc(const float* __restrict__ Wfc, const float* __restrict__ bfc,
                     float* __restrict__ out) {
    int g = threadIdx.x;
    if (g >= GG) return;
    float s = 0.f;
#pragma unroll
    for (int j = 0; j < 128; j++) s += g_pooled[g * 128 + j] * Wfc[j];
    out[g] = s / fmaxf(g_cnt[g], 1.0f) + bfc[0];
}

// ---------------- launch ----------------
extern "C" void kernel_launch(void* const* d_in, const int* in_sizes, int n_in,
                              void* d_out, int out_size) {
    const float* x     = (const float*)d_in[0];
    const int*   ei    = (const int*)d_in[1];
    const float* eattr = (const float*)d_in[2];
    const int*   batch = (const int*)d_in[3];
    const float* W1    = (const float*)d_in[4];
    const float* b1    = (const float*)d_in[5];
    const float* W2    = (const float*)d_in[6];
    const float* b2    = (const float*)d_in[7];
    const float* We1   = (const float*)d_in[8];
    const float* be1   = (const float*)d_in[9];
    const float* We2   = (const float*)d_in[10];
    const float* be2   = (const float*)d_in[11];
    const float* Watt  = (const float*)d_in[12];
    const float* Wfc   = (const float*)d_in[14];
    const float* bfc   = (const float*)d_in[15];
    float* out = (float*)d_out;

    float *bufA, *bufB, *bufC;
    cudaGetSymbolAddress((void**)&bufA, g_bufA);
    cudaGetSymbolAddress((void**)&bufB, g_bufB);
    cudaGetSymbolAddress((void**)&bufC, g_bufC);

    const int T = 256;

    k_init<<<(NN + T - 1) / T, T>>>();
    k_deg_count<<<(EE + T - 1) / T, T>>>(ei);
    k_dinv<<<(NN + T - 1) / T, T>>>();
    k_cnt<<<(NN + T - 1) / T, T>>>(batch);

    // conv1
    k_gemm_conv<<<(NN + 63) / 64, 256>>>(x, W1, b1, bufA, bufC, NN);
    {
        long long tc = (long long)EE * 32;
        k_conv_scatter<<<(unsigned)((tc + T - 1) / T), T>>>(ei, bufA, bufC);
    }
    // h = elu(conv1); per-node attention dots; zero agg buffer (bufC)
    k_elu_att<<<(NN * 32 + T - 1) / T, T>>>(bufC, bufB, bufC, Watt);

    // global softmax over E+N logits
    k_logit_max<<<512, 256>>>(ei);
    k_logit_sum<<<512, 256>>>(ei);

    // edge MLP layer 1 + att-weighted scatter of hidden into bufC
    k_edge_hidden_scatter<<<EE / 64, 256>>>(eattr, ei, We1, be1, bufC);

    // node-side We2 application: h += agg@We2 + attsum*be2
    k_gemm_apply<<<(NN + 63) / 64, 256>>>(bufC, We2, be2, bufB, NN);

    // conv2
    k_gemm_conv<<<(NN + 63) / 64, 256>>>(bufB, W2, b2, bufA, bufC, NN);
    {
        long long tc = (long long)EE * 32;
        k_conv_scatter<<<(unsigned)((tc + T - 1) / T), T>>>(ei, bufA, bufC);
    }

    // elu + global mean pool + fc
    {
        int totalChunks = (NN + 7) / 8;
        k_elu_pool<<<(totalChunks * 128 + T - 1) / T, T>>>(bufC, batch);
    }
    k_fc<<<1, 64>>>(Wfc, bfc, out);
}